// round 2
// baseline (speedup 1.0000x reference)
#include <cuda_runtime.h>

// GACRF fused kernel: softmax(C=19) -> encode(G=8) -> 3x3 dynamic local filter
// -> decode -> logit - result.  Single kernel, tiled with 1-pixel halo in smem.
//
// R1 change vs R0: kill the 255-reg blow-up (rr-loop unroll) and force 3
// CTAs/SM via __launch_bounds__ -> occupancy 12.3% -> ~37%.
//
// Shapes (fixed): b=4, C=19, G=8, H=W=512, K=3.

#define BATCH 4
#define NC 19
#define NG 8
#define IMH 512
#define IMW 512
#define HW (IMH * IMW)

#define TW 64          // tile width  (output)
#define TH 16          // tile height (output)
#define EW (TW + 2)    // 66, extended (halo) width
#define EH (TH + 2)    // 18, extended height
#define NTHREADS 256

__global__ __launch_bounds__(NTHREADS, 3) void gacrf_fused_kernel(
    const float* __restrict__ Fk,     // [b,9,H,W]
    const float* __restrict__ logit,  // [b,C,H,W]
    const float* __restrict__ matrix, // [G,C]
    float* __restrict__ out)          // [b,C,H,w]
{
    __shared__ float Esh[NG][NC];          // encoding matrix, 608 B
    __shared__ float Qg[NG][EH][EW];       // SoA group features, 38016 B

    const int tid = threadIdx.x;
    const int bx = blockIdx.x, by = blockIdx.y, bz = blockIdx.z;

    // ---- E = softmax over G of 100*matrix, per column c (19 threads) ----
    if (tid < NC) {
        const int c = tid;
        float m[NG];
        float mx = -1e30f;
        #pragma unroll
        for (int g = 0; g < NG; g++) {
            m[g] = 100.0f * matrix[g * NC + c];
            mx = fmaxf(mx, m[g]);
        }
        float s = 0.0f;
        #pragma unroll
        for (int g = 0; g < NG; g++) {
            m[g] = __expf(m[g] - mx);
            s += m[g];
        }
        const float r = 1.0f / s;
        #pragma unroll
        for (int g = 0; g < NG; g++) Esh[g][c] = m[g] * r;
    }
    __syncthreads();

    const int x0 = bx * TW;
    const int y0 = by * TH;
    const float* __restrict__ logit_b = logit + (size_t)bz * NC * HW;

    // ---- Phase 1: Qg for extended tile (softmax + encode), zero-pad OOB ----
    #pragma unroll 1
    for (int idx = tid; idx < EW * EH; idx += NTHREADS) {
        const int ey = idx / EW;
        const int ex = idx - ey * EW;
        const int gy = y0 + ey - 1;
        const int gx = x0 + ex - 1;

        float acc[NG];
        #pragma unroll
        for (int g = 0; g < NG; g++) acc[g] = 0.0f;

        if ((unsigned)gy < IMH && (unsigned)gx < IMW) {
            const float* __restrict__ p = logit_b + (size_t)gy * IMW + gx;
            float s = 0.0f;
            #pragma unroll
            for (int c = 0; c < NC; c++) {
                // logits are ~N(0,1): exp without max-subtraction is safe in fp32
                const float e = __expf(p[(size_t)c * HW]);
                s += e;
                #pragma unroll
                for (int g = 0; g < NG; g++)
                    acc[g] = fmaf(Esh[g][c], e, acc[g]);
            }
            const float r = __frcp_rn(s);
            #pragma unroll
            for (int g = 0; g < NG; g++) acc[g] *= r;
        }
        #pragma unroll
        for (int g = 0; g < NG; g++) Qg[g][ey][ex] = acc[g];
    }
    __syncthreads();

    // ---- Phase 2: 3x3 filter + decode + subtract ----
    const int x  = tid & (TW - 1);     // 0..63 (lane-consecutive -> coalesced/conflict-free)
    const int ty = tid >> 6;           // 0..3
    const float* __restrict__ F_b  = Fk  + (size_t)bz * 9 * HW;
    float* __restrict__       out_b = out + (size_t)bz * NC * HW;

    #pragma unroll 1
    for (int rr = 0; rr < TH / 4; rr++) {
        const int y  = ty + rr * 4;    // local row 0..15
        const int gy = y0 + y;
        const int gx = x0 + x;

        // 9 per-pixel filter taps (coalesced LDG, channel-strided)
        float f[9];
        const float* __restrict__ fp = F_b + (size_t)gy * IMW + gx;
        #pragma unroll
        for (int k = 0; k < 9; k++) f[k] = fp[(size_t)k * HW];

        // filtered group features from smem (conflict-free: 4B lane stride)
        float filt[NG];
        #pragma unroll
        for (int g = 0; g < NG; g++) {
            float a = 0.0f;
            #pragma unroll
            for (int dy = 0; dy < 3; dy++)
                #pragma unroll
                for (int dx = 0; dx < 3; dx++)
                    a = fmaf(f[dy * 3 + dx], Qg[g][y + dy][x + dx], a);
            filt[g] = a;
        }

        // decode (E^T) and subtract from logit
        const float* __restrict__ lp = logit_b + (size_t)gy * IMW + gx;
        float* __restrict__       op = out_b   + (size_t)gy * IMW + gx;
        #pragma unroll
        for (int c = 0; c < NC; c++) {
            float a = 0.0f;
            #pragma unroll
            for (int g = 0; g < NG; g++)
                a = fmaf(Esh[g][c], filt[g], a);
            op[(size_t)c * HW] = lp[(size_t)c * HW] - a;
        }
    }
}

extern "C" void kernel_launch(void* const* d_in, const int* in_sizes, int n_in,
                              void* d_out, int out_size) {
    // Bind inputs by element count (robust to ordering):
    //   F:      4*9*512*512  = 9437184
    //   logit:  4*19*512*512 = 19922944
    //   matrix: 8*19         = 152
    const float* F      = nullptr;
    const float* logit  = nullptr;
    const float* matrix = nullptr;
    for (int i = 0; i < n_in; i++) {
        if (in_sizes[i] == 9437184)       F      = (const float*)d_in[i];
        else if (in_sizes[i] == 19922944) logit  = (const float*)d_in[i];
        else if (in_sizes[i] == 152)      matrix = (const float*)d_in[i];
    }
    float* out = (float*)d_out;

    dim3 grid(IMW / TW, IMH / TH, BATCH);   // (8, 32, 4)
    gacrf_fused_kernel<<<grid, NTHREADS>>>(F, logit, matrix, out);
}

// round 3
// speedup vs baseline: 1.8958x; 1.8958x over previous
#include <cuda_runtime.h>

// GACRF fused kernel: softmax(C=19) -> encode(G=8) -> 3x3 dynamic local filter
// -> decode -> logit - result.  Single kernel, tiled with 1-pixel halo in smem.
//
// R2: MLP x occupancy balance. R0 (255 regs, 1 CTA/SM, deep load batching) ran
// 80us; R1 (unroll 1, 80-reg cap, 3 CTA/SM) destroyed MLP and regressed to
// 158us. This round: 128-reg budget (2 CTA/SM) with controlled 2-row batching
// in phase 2 and compiler-chosen batching in phase 1.
//
// Shapes (fixed): b=4, C=19, G=8, H=W=512, K=3.

#define BATCH 4
#define NC 19
#define NG 8
#define IMH 512
#define IMW 512
#define HW (IMH * IMW)

#define TW 64          // tile width  (output)
#define TH 16          // tile height (output)
#define EW (TW + 2)    // 66, extended (halo) width
#define EH (TH + 2)    // 18, extended height
#define NTHREADS 256

__global__ __launch_bounds__(NTHREADS, 2) void gacrf_fused_kernel(
    const float* __restrict__ Fk,     // [b,9,H,W]
    const float* __restrict__ logit,  // [b,C,H,W]
    const float* __restrict__ matrix, // [G,C]
    float* __restrict__ out)          // [b,C,H,W]
{
    __shared__ float Esh[NG][NC];          // encoding matrix, 608 B
    __shared__ float Qg[NG][EH][EW];       // SoA group features, 38016 B

    const int tid = threadIdx.x;
    const int bx = blockIdx.x, by = blockIdx.y, bz = blockIdx.z;

    // ---- E = softmax over G of 100*matrix, per column c (19 threads) ----
    if (tid < NC) {
        const int c = tid;
        float m[NG];
        float mx = -1e30f;
        #pragma unroll
        for (int g = 0; g < NG; g++) {
            m[g] = 100.0f * matrix[g * NC + c];
            mx = fmaxf(mx, m[g]);
        }
        float s = 0.0f;
        #pragma unroll
        for (int g = 0; g < NG; g++) {
            m[g] = __expf(m[g] - mx);
            s += m[g];
        }
        const float r = 1.0f / s;
        #pragma unroll
        for (int g = 0; g < NG; g++) Esh[g][c] = m[g] * r;
    }
    __syncthreads();

    const int x0 = bx * TW;
    const int y0 = by * TH;
    const float* __restrict__ logit_b = logit + (size_t)bz * NC * HW;

    // ---- Phase 1: Qg for extended tile (softmax + encode), zero-pad OOB ----
    // Compiler-chosen unrolling (batches ~2 pixels' loads under the reg budget).
    for (int idx = tid; idx < EW * EH; idx += NTHREADS) {
        const int ey = idx / EW;
        const int ex = idx - ey * EW;
        const int gy = y0 + ey - 1;
        const int gx = x0 + ex - 1;

        float acc[NG];
        #pragma unroll
        for (int g = 0; g < NG; g++) acc[g] = 0.0f;

        if ((unsigned)gy < IMH && (unsigned)gx < IMW) {
            const float* __restrict__ p = logit_b + (size_t)gy * IMW + gx;
            float s = 0.0f;
            #pragma unroll
            for (int c = 0; c < NC; c++) {
                // logits are ~N(0,1): exp without max-subtraction is safe in fp32
                const float e = __expf(p[(size_t)c * HW]);
                s += e;
                #pragma unroll
                for (int g = 0; g < NG; g++)
                    acc[g] = fmaf(Esh[g][c], e, acc[g]);
            }
            const float r = __frcp_rn(s);
            #pragma unroll
            for (int g = 0; g < NG; g++) acc[g] *= r;
        }
        #pragma unroll
        for (int g = 0; g < NG; g++) Qg[g][ey][ex] = acc[g];
    }
    __syncthreads();

    // ---- Phase 2: 3x3 filter + decode + subtract, 2 rows per iteration ----
    const int x  = tid & (TW - 1);     // 0..63 (lane-consecutive -> coalesced/conflict-free)
    const int ty = tid >> 6;           // 0..3
    const float* __restrict__ F_b  = Fk  + (size_t)bz * 9 * HW;
    float* __restrict__       out_b = out + (size_t)bz * NC * HW;
    const int gx = x0 + x;

    #pragma unroll 2
    for (int rr = 0; rr < TH / 4; rr++) {
        const int y  = ty + rr * 4;    // local row 0..15
        const int gy = y0 + y;

        // 9 per-pixel filter taps (coalesced LDG, channel-strided)
        float f[9];
        const float* __restrict__ fp = F_b + (size_t)gy * IMW + gx;
        #pragma unroll
        for (int k = 0; k < 9; k++) f[k] = fp[(size_t)k * HW];

        // filtered group features from smem (conflict-free: 4B lane stride)
        float filt[NG];
        #pragma unroll
        for (int g = 0; g < NG; g++) {
            float a = 0.0f;
            #pragma unroll
            for (int dy = 0; dy < 3; dy++)
                #pragma unroll
                for (int dx = 0; dx < 3; dx++)
                    a = fmaf(f[dy * 3 + dx], Qg[g][y + dy][x + dx], a);
            filt[g] = a;
        }

        // decode (E^T) and subtract from logit
        const float* __restrict__ lp = logit_b + (size_t)gy * IMW + gx;
        float* __restrict__       op = out_b   + (size_t)gy * IMW + gx;
        #pragma unroll
        for (int c = 0; c < NC; c++) {
            float a = 0.0f;
            #pragma unroll
            for (int g = 0; g < NG; g++)
                a = fmaf(Esh[g][c], filt[g], a);
            op[(size_t)c * HW] = lp[(size_t)c * HW] - a;
        }
    }
}

extern "C" void kernel_launch(void* const* d_in, const int* in_sizes, int n_in,
                              void* d_out, int out_size) {
    // Bind inputs by element count (robust to ordering):
    //   F:      4*9*512*512  = 9437184
    //   logit:  4*19*512*512 = 19922944
    //   matrix: 8*19         = 152
    const float* F      = nullptr;
    const float* logit  = nullptr;
    const float* matrix = nullptr;
    for (int i = 0; i < n_in; i++) {
        if (in_sizes[i] == 9437184)       F      = (const float*)d_in[i];
        else if (in_sizes[i] == 19922944) logit  = (const float*)d_in[i];
        else if (in_sizes[i] == 152)      matrix = (const float*)d_in[i];
    }
    float* out = (float*)d_out;

    dim3 grid(IMW / TW, IMH / TH, BATCH);   // (8, 32, 4)
    gacrf_fused_kernel<<<grid, NTHREADS>>>(F, logit, matrix, out);
}

// round 4
// speedup vs baseline: 1.9716x; 1.0400x over previous
#include <cuda_runtime.h>

// GACRF fused: softmax(C=19) -> encode(G=8) -> 3x3 dynamic filter -> decode ->
// logit - result.
//
// R3: x4 vectorization in x. Every thread handles 4 consecutive pixels via
// float4 LDG/STG/LDS. Smem tile widened to 72 cols (global [x0-4, x0+68)) so
// both global loads and smem accesses stay 16B-aligned despite the -1 halo.
// Cuts issue slots/pixel ~2x (scalar LDG 47->~3 vector, filter LDS 72->18,
// E-operand LDS amortized x4).
//
// Shapes (fixed): b=4, C=19, G=8, H=W=512, K=3.

#define BATCH 4
#define NC 19
#define NG 8
#define IMH 512
#define IMW 512
#define HW (IMH * IMW)

#define TW 64            // output tile width
#define TH 16            // output tile height
#define EH (TH + 2)      // 18 extended rows (global y0-1 .. y0+16)
#define EWP 72           // padded extended width, covers global [x0-4, x0+68)
#define NGX (EWP / 4)    // 18 col-groups of 4
#define NTHREADS 256

__global__ __launch_bounds__(NTHREADS, 2) void gacrf_fused_kernel(
    const float* __restrict__ Fk,     // [b,9,H,W]
    const float* __restrict__ logit,  // [b,C,H,W]
    const float* __restrict__ matrix, // [G,C]
    float* __restrict__ out)          // [b,C,H,W]
{
    __shared__ float Esh[NG][NC];
    __shared__ __align__(16) float Qg[NG][EH][EWP];   // 41472 B

    const int tid = threadIdx.x;
    const int bx = blockIdx.x, by = blockIdx.y, bz = blockIdx.z;

    // ---- E = softmax over G of 100*matrix ----
    if (tid < NC) {
        const int c = tid;
        float m[NG];
        float mx = -1e30f;
        #pragma unroll
        for (int g = 0; g < NG; g++) {
            m[g] = 100.0f * matrix[g * NC + c];
            mx = fmaxf(mx, m[g]);
        }
        float s = 0.0f;
        #pragma unroll
        for (int g = 0; g < NG; g++) { m[g] = __expf(m[g] - mx); s += m[g]; }
        const float r = 1.0f / s;
        #pragma unroll
        for (int g = 0; g < NG; g++) Esh[g][c] = m[g] * r;
    }
    __syncthreads();

    const int x0 = bx * TW;
    const int y0 = by * TH;
    const float* __restrict__ logit_b = logit + (size_t)bz * NC * HW;

    // ---- Phase 1: softmax+encode for extended tile, 4 pixels/thread ----
    // ext col e <-> global x0 - 4 + e ; ext row r <-> global y0 - 1 + r
    #pragma unroll 1
    for (int idx = tid; idx < EH * NGX; idx += NTHREADS) {
        const int r  = idx / NGX;
        const int j  = idx - r * NGX;
        const int gy = y0 + r - 1;
        const int gxb = x0 - 4 + 4 * j;

        float4 acc[NG];
        #pragma unroll
        for (int g = 0; g < NG; g++) acc[g] = make_float4(0.f, 0.f, 0.f, 0.f);

        if ((unsigned)gy < IMH) {
            if (gxb >= 0 && gxb + 3 < IMW) {
                // fast aligned-vector path
                const float* __restrict__ p = logit_b + (size_t)gy * IMW + gxb;
                float4 s = make_float4(0.f, 0.f, 0.f, 0.f);
                #pragma unroll
                for (int c = 0; c < NC; c++) {
                    const float4 v = *(const float4*)(p + (size_t)c * HW);
                    const float e0 = __expf(v.x), e1 = __expf(v.y);
                    const float e2 = __expf(v.z), e3 = __expf(v.w);
                    s.x += e0; s.y += e1; s.z += e2; s.w += e3;
                    #pragma unroll
                    for (int g = 0; g < NG; g++) {
                        const float E = Esh[g][c];
                        acc[g].x = fmaf(E, e0, acc[g].x);
                        acc[g].y = fmaf(E, e1, acc[g].y);
                        acc[g].z = fmaf(E, e2, acc[g].z);
                        acc[g].w = fmaf(E, e3, acc[g].w);
                    }
                }
                const float r0 = __frcp_rn(s.x), r1 = __frcp_rn(s.y);
                const float r2 = __frcp_rn(s.z), r3 = __frcp_rn(s.w);
                #pragma unroll
                for (int g = 0; g < NG; g++) {
                    acc[g].x *= r0; acc[g].y *= r1;
                    acc[g].z *= r2; acc[g].w *= r3;
                }
            } else {
                // rare image-border path, per-element guarded
                #pragma unroll
                for (int i = 0; i < 4; i++) {
                    const int gx = gxb + i;
                    if ((unsigned)gx < IMW) {
                        const float* __restrict__ p = logit_b + (size_t)gy * IMW + gx;
                        float a2[NG];
                        #pragma unroll
                        for (int g = 0; g < NG; g++) a2[g] = 0.f;
                        float s = 0.f;
                        #pragma unroll 1
                        for (int c = 0; c < NC; c++) {
                            const float e = __expf(p[(size_t)c * HW]);
                            s += e;
                            #pragma unroll
                            for (int g = 0; g < NG; g++)
                                a2[g] = fmaf(Esh[g][c], e, a2[g]);
                        }
                        const float rr = __frcp_rn(s);
                        #pragma unroll
                        for (int g = 0; g < NG; g++) {
                            const float v = a2[g] * rr;
                            if (i == 0) acc[g].x = v;
                            else if (i == 1) acc[g].y = v;
                            else if (i == 2) acc[g].z = v;
                            else acc[g].w = v;
                        }
                    }
                }
            }
        }
        #pragma unroll
        for (int g = 0; g < NG; g++)
            *(float4*)&Qg[g][r][4 * j] = acc[g];
    }
    __syncthreads();

    // ---- Phase 2: 3x3 filter + decode + subtract, 4 pixels/thread ----
    // 16 groups/row x 16 rows = 256 threads, one group each.
    {
        const int y  = tid >> 4;           // 0..15
        const int xg = (tid & 15) << 2;    // 0,4,..,60 (local x of group base)
        const int gy = y0 + y;

        const float* __restrict__ F_b = Fk + (size_t)bz * 9 * HW;
        float* __restrict__ out_b     = out + (size_t)bz * NC * HW;

        // 9 per-pixel filter taps, vectorized (x0+xg is 16B aligned)
        float4 f4[9];
        const float* __restrict__ fp = F_b + (size_t)gy * IMW + (x0 + xg);
        #pragma unroll
        for (int k = 0; k < 9; k++) f4[k] = *(const float4*)(fp + (size_t)k * HW);

        // filter: pixel (xg+i) taps ext cols xg+3+i+dj, rows y..y+2
        float4 filt[NG];
        #pragma unroll
        for (int g = 0; g < NG; g++) filt[g] = make_float4(0.f, 0.f, 0.f, 0.f);

        #pragma unroll
        for (int g = 0; g < NG; g++) {
            #pragma unroll
            for (int dr = 0; dr < 3; dr++) {
                const float* __restrict__ qrow = &Qg[g][y + dr][xg + 3];
                const float  q0 = qrow[0];
                const float4 qm = *(const float4*)(qrow + 1);   // cols xg+4..xg+7
                const float  q5 = qrow[5];
                const float4 fa = f4[dr * 3 + 0];
                const float4 fb = f4[dr * 3 + 1];
                const float4 fc = f4[dr * 3 + 2];
                filt[g].x = fmaf(fa.x, q0,   fmaf(fb.x, qm.x, fmaf(fc.x, qm.y, filt[g].x)));
                filt[g].y = fmaf(fa.y, qm.x, fmaf(fb.y, qm.y, fmaf(fc.y, qm.z, filt[g].y)));
                filt[g].z = fmaf(fa.z, qm.y, fmaf(fb.z, qm.z, fmaf(fc.z, qm.w, filt[g].z)));
                filt[g].w = fmaf(fa.w, qm.z, fmaf(fb.w, qm.w, fmaf(fc.w, q5,   filt[g].w)));
            }
        }

        // decode (E^T) + subtract + store
        const float* __restrict__ lp = logit_b + (size_t)gy * IMW + (x0 + xg);
        float* __restrict__       op = out_b   + (size_t)gy * IMW + (x0 + xg);
        #pragma unroll
        for (int c = 0; c < NC; c++) {
            float4 a = make_float4(0.f, 0.f, 0.f, 0.f);
            #pragma unroll
            for (int g = 0; g < NG; g++) {
                const float E = Esh[g][c];
                a.x = fmaf(E, filt[g].x, a.x);
                a.y = fmaf(E, filt[g].y, a.y);
                a.z = fmaf(E, filt[g].z, a.z);
                a.w = fmaf(E, filt[g].w, a.w);
            }
            const float4 l4 = *(const float4*)(lp + (size_t)c * HW);
            float4 o;
            o.x = l4.x - a.x; o.y = l4.y - a.y;
            o.z = l4.z - a.z; o.w = l4.w - a.w;
            *(float4*)(op + (size_t)c * HW) = o;
        }
    }
}

extern "C" void kernel_launch(void* const* d_in, const int* in_sizes, int n_in,
                              void* d_out, int out_size) {
    // Bind inputs by element count (robust to ordering):
    //   F: 9437184, logit: 19922944, matrix: 152
    const float* F      = nullptr;
    const float* logit  = nullptr;
    const float* matrix = nullptr;
    for (int i = 0; i < n_in; i++) {
        if (in_sizes[i] == 9437184)       F      = (const float*)d_in[i];
        else if (in_sizes[i] == 19922944) logit  = (const float*)d_in[i];
        else if (in_sizes[i] == 152)      matrix = (const float*)d_in[i];
    }
    float* out = (float*)d_out;

    dim3 grid(IMW / TW, IMH / TH, BATCH);   // (8, 32, 4)
    gacrf_fused_kernel<<<grid, NTHREADS>>>(F, logit, matrix, out);
}